// round 3
// baseline (speedup 1.0000x reference)
#include <cuda_runtime.h>
#include <math.h>

#define BDIM   4
#define TXQ    4096
#define TXFK   256
#define DMODEL 1024
#define DTEXT  768
#define NHEADS 16
#define HDIM   64
#define MQ     (BDIM*TXQ)     // 16384
#define MKV    (BDIM*TXFK)    // 1024
#define DFF    4096
#define ATT_SCALE 0.125f      // 64^-0.5

// ---------------- scratch (device globals; no allocation allowed) -------------
__device__ float g_q   [(size_t)MQ  * DMODEL];   // 64 MB
__device__ float g_k   [(size_t)MKV * DMODEL];   // 4 MB
__device__ float g_v   [(size_t)MKV * DMODEL];   // 4 MB
__device__ float g_attn[(size_t)MQ  * DMODEL];   // 64 MB
__device__ float g_res [(size_t)MQ  * DMODEL];   // out = attn@Wo+bo (residual base)
__device__ float g_ln  [(size_t)MQ  * DMODEL];   // LayerNorm(out)
__device__ float g_h   [(size_t)MQ  * DFF];      // GELU(ln@W1+b1), 256 MB

__device__ __forceinline__ float gelu_exact(float v) {
    return 0.5f * v * (1.0f + erff(v * 0.7071067811865476f));
}

// ---------------- generic fp32 SGEMM: C = act(A@W + bias) [+ res1 + res2] ----
// A: [M,K] row-major, W: [K,N] row-major, C: [M,N] row-major.
// BM=BN=128, BK=16, 256 threads, 8x8 per thread. All shapes divisible.
template<int ACT, int NRES>
__global__ void __launch_bounds__(256, 2) sgemm_kernel(
    int M, int N, int K,
    const float* __restrict__ A, const float* __restrict__ W,
    const float* __restrict__ bias,
    const float* __restrict__ res1, const float* __restrict__ res2,
    float* __restrict__ C)
{
    const int BM = 128, BN = 128, BK = 16;
    __shared__ float As[BK][BM];
    __shared__ float Bs[BK][BN];

    const int tid = threadIdx.x;
    const int tx  = tid & 15;        // 0..15 -> col block
    const int ty  = tid >> 4;        // 0..15 -> row block
    const int bx  = blockIdx.x;      // N tile
    const int by  = blockIdx.y;      // M tile

    // A load mapping: 128 rows x 16 cols -> 512 float4; 2 per thread
    const int a_row  = tid >> 2;          // 0..63 (also +64)
    const int a_col4 = (tid & 3) * 4;     // 0,4,8,12
    // W load mapping: 16 rows x 128 cols -> 512 float4; 2 per thread
    const int b_row  = tid >> 5;          // 0..7 (also +8)
    const int b_col4 = (tid & 31) * 4;    // 0..124

    const float* Ab = A + (size_t)by * BM * K;
    const float* Wb = W + (size_t)bx * BN;

    float acc[8][8];
#pragma unroll
    for (int i = 0; i < 8; i++)
#pragma unroll
        for (int j = 0; j < 8; j++) acc[i][j] = 0.0f;

    for (int k0 = 0; k0 < K; k0 += BK) {
        float4 a0 = *(const float4*)(Ab + (size_t)a_row        * K + k0 + a_col4);
        float4 a1 = *(const float4*)(Ab + (size_t)(a_row + 64) * K + k0 + a_col4);
        float4 w0 = *(const float4*)(Wb + (size_t)(k0 + b_row    ) * N + b_col4);
        float4 w1 = *(const float4*)(Wb + (size_t)(k0 + b_row + 8) * N + b_col4);

        As[a_col4 + 0][a_row     ] = a0.x;
        As[a_col4 + 1][a_row     ] = a0.y;
        As[a_col4 + 2][a_row     ] = a0.z;
        As[a_col4 + 3][a_row     ] = a0.w;
        As[a_col4 + 0][a_row + 64] = a1.x;
        As[a_col4 + 1][a_row + 64] = a1.y;
        As[a_col4 + 2][a_row + 64] = a1.z;
        As[a_col4 + 3][a_row + 64] = a1.w;
        *(float4*)&Bs[b_row    ][b_col4] = w0;
        *(float4*)&Bs[b_row + 8][b_col4] = w1;
        __syncthreads();

#pragma unroll
        for (int kk = 0; kk < BK; kk++) {
            float ra[8], rb[8];
            *(float4*)(ra    ) = *(const float4*)&As[kk][ty * 8    ];
            *(float4*)(ra + 4) = *(const float4*)&As[kk][ty * 8 + 4];
            *(float4*)(rb    ) = *(const float4*)&Bs[kk][tx * 8    ];
            *(float4*)(rb + 4) = *(const float4*)&Bs[kk][tx * 8 + 4];
#pragma unroll
            for (int i = 0; i < 8; i++)
#pragma unroll
                for (int j = 0; j < 8; j++)
                    acc[i][j] += ra[i] * rb[j];
        }
        __syncthreads();
    }

    const int row0 = by * BM + ty * 8;
    const int col0 = bx * BN + tx * 8;
#pragma unroll
    for (int i = 0; i < 8; i++) {
        size_t base = (size_t)(row0 + i) * N + col0;
        float4 o[2];
#pragma unroll
        for (int jj = 0; jj < 2; jj++) {
            float vv[4];
#pragma unroll
            for (int j = 0; j < 4; j++) {
                int jc = jj * 4 + j;
                float v = acc[i][jc] + bias[col0 + jc];
                if (ACT == 1) v = gelu_exact(v);
                if (NRES >= 1) v += res1[base + jc];
                if (NRES >= 2) v += res2[base + jc];
                vv[j] = v;
            }
            o[jj] = make_float4(vv[0], vv[1], vv[2], vv[3]);
        }
        *(float4*)(C + base)     = o[0];
        *(float4*)(C + base + 4) = o[1];
    }
}

// ---------------- attention: per (b, h, q-chunk) block ------------------------
// Q: [MQ, DMODEL] (head h occupies cols h*64..), K/V: [MKV, DMODEL].
// Whole 256x64 K and V head-tiles live in padded smem; softmax over all 256 keys.
#define QPB 256
#define KPAD 65

__global__ void __launch_bounds__(256) attn_kernel(
    const float* __restrict__ Q, const float* __restrict__ K,
    const float* __restrict__ V, float* __restrict__ O)
{
    extern __shared__ float sm[];
    float* Ks = sm;                  // 256*65
    float* Vs = Ks + 256 * KPAD;     // 256*65
    float* qs = Vs + 256 * KPAD;     // 8*64
    float* ps = qs + 8 * 64;         // 8*256

    const int nchunk = TXQ / QPB;    // 16
    const int bid   = blockIdx.x;
    const int chunk = bid % nchunk;
    const int h     = (bid / nchunk) % NHEADS;
    const int b     = bid / (nchunk * NHEADS);

    const int tid  = threadIdx.x;
    const int lane = tid & 31;
    const int w    = tid >> 5;

    // load K,V head tiles (256 rows x 64 cols) into padded smem
    for (int i = tid; i < 256 * 16; i += 256) {
        int j  = i >> 4;
        int dq = (i & 15) * 4;
        size_t gbase = (size_t)(b * TXFK + j) * DMODEL + h * HDIM + dq;
        float4 kv = *(const float4*)(K + gbase);
        float4 vv = *(const float4*)(V + gbase);
        Ks[j * KPAD + dq + 0] = kv.x; Ks[j * KPAD + dq + 1] = kv.y;
        Ks[j * KPAD + dq + 2] = kv.z; Ks[j * KPAD + dq + 3] = kv.w;
        Vs[j * KPAD + dq + 0] = vv.x; Vs[j * KPAD + dq + 1] = vv.y;
        Vs[j * KPAD + dq + 2] = vv.z; Vs[j * KPAD + dq + 3] = vv.w;
    }
    __syncthreads();

    for (int qi = 0; qi < 32; qi++) {
        const int qlocal = w * 32 + qi;
        const size_t qrow = (size_t)b * TXQ + (size_t)chunk * QPB + qlocal;
        const float* qp = Q + qrow * DMODEL + h * HDIM;
        qs[w * 64 + lane]      = qp[lane];
        qs[w * 64 + lane + 32] = qp[lane + 32];
        __syncwarp();

        // scores: lane owns keys j = lane + 32*c (conflict-free via KPAD=65)
        float s[8];
#pragma unroll
        for (int c = 0; c < 8; c++) s[c] = 0.0f;
        for (int d = 0; d < 64; d++) {
            float qd = qs[w * 64 + d];
#pragma unroll
            for (int c = 0; c < 8; c++)
                s[c] += qd * Ks[(lane + 32 * c) * KPAD + d];
        }
#pragma unroll
        for (int c = 0; c < 8; c++) s[c] *= ATT_SCALE;

        float mx = s[0];
#pragma unroll
        for (int c = 1; c < 8; c++) mx = fmaxf(mx, s[c]);
#pragma unroll
        for (int o = 16; o; o >>= 1) mx = fmaxf(mx, __shfl_xor_sync(~0u, mx, o));

        float sum = 0.0f;
#pragma unroll
        for (int c = 0; c < 8; c++) { s[c] = __expf(s[c] - mx); sum += s[c]; }
#pragma unroll
        for (int o = 16; o; o >>= 1) sum += __shfl_xor_sync(~0u, sum, o);
        float inv = 1.0f / sum;

#pragma unroll
        for (int c = 0; c < 8; c++) ps[w * 256 + lane + 32 * c] = s[c] * inv;
        __syncwarp();

        // output: lane owns dims d=lane and d=lane+32
        float o0 = 0.0f, o1 = 0.0f;
        for (int j = 0; j < 256; j++) {
            float p = ps[w * 256 + j];
            o0 += p * Vs[j * KPAD + lane];
            o1 += p * Vs[j * KPAD + lane + 32];
        }
        float* op = O + qrow * DMODEL + h * HDIM;
        op[lane]      = o0;
        op[lane + 32] = o1;
        __syncwarp();   // protect qs/ps reuse next iteration
    }
}

// ---------------- LayerNorm over rows of [MQ, 1024] ---------------------------
__global__ void __launch_bounds__(256) ln_kernel(
    const float* __restrict__ X, const float* __restrict__ gw,
    const float* __restrict__ bw, float* __restrict__ Y)
{
    const int row = blockIdx.x;
    const int t = threadIdx.x;
    float4 v = ((const float4*)(X + (size_t)row * DMODEL))[t];
    float s1 = v.x + v.y + v.z + v.w;
    float s2 = v.x * v.x + v.y * v.y + v.z * v.z + v.w * v.w;
#pragma unroll
    for (int o = 16; o; o >>= 1) {
        s1 += __shfl_xor_sync(~0u, s1, o);
        s2 += __shfl_xor_sync(~0u, s2, o);
    }
    __shared__ float r1[8], r2[8];
    const int w = t >> 5, lane = t & 31;
    if (lane == 0) { r1[w] = s1; r2[w] = s2; }
    __syncthreads();
    if (w == 0) {
        s1 = (lane < 8) ? r1[lane] : 0.0f;
        s2 = (lane < 8) ? r2[lane] : 0.0f;
#pragma unroll
        for (int o = 4; o; o >>= 1) {
            s1 += __shfl_xor_sync(~0u, s1, o);
            s2 += __shfl_xor_sync(~0u, s2, o);
        }
        if (lane == 0) { r1[0] = s1; r2[0] = s2; }
    }
    __syncthreads();
    const float mean = r1[0] * (1.0f / DMODEL);
    const float var  = r2[0] * (1.0f / DMODEL) - mean * mean;
    const float rstd = rsqrtf(var + 1e-5f);
    float4 g4 = ((const float4*)gw)[t];
    float4 b4 = ((const float4*)bw)[t];
    float4 o;
    o.x = (v.x - mean) * rstd * g4.x + b4.x;
    o.y = (v.y - mean) * rstd * g4.y + b4.y;
    o.z = (v.z - mean) * rstd * g4.z + b4.z;
    o.w = (v.w - mean) * rstd * g4.w + b4.w;
    ((float4*)(Y + (size_t)row * DMODEL))[t] = o;
}

// ---------------- launch -----------------------------------------------------
extern "C" void kernel_launch(void* const* d_in, const int* in_sizes, int n_in,
                              void* d_out, int out_size)
{
    const float* x    = (const float*)d_in[0];
    const float* xf   = (const float*)d_in[1];
    const float* Wq   = (const float*)d_in[2];
    const float* bq   = (const float*)d_in[3];
    const float* Wk   = (const float*)d_in[4];
    const float* bk   = (const float*)d_in[5];
    const float* Wv   = (const float*)d_in[6];
    const float* bv   = (const float*)d_in[7];
    const float* Wo   = (const float*)d_in[8];
    const float* bo   = (const float*)d_in[9];
    const float* ln_g = (const float*)d_in[10];
    const float* ln_b = (const float*)d_in[11];
    const float* W1   = (const float*)d_in[12];
    const float* b1   = (const float*)d_in[13];
    const float* W2   = (const float*)d_in[14];
    const float* b2   = (const float*)d_in[15];
    float* out = (float*)d_out;

    float *q, *k, *v, *attn, *res, *ln, *hbuf;
    cudaGetSymbolAddress((void**)&q,    g_q);
    cudaGetSymbolAddress((void**)&k,    g_k);
    cudaGetSymbolAddress((void**)&v,    g_v);
    cudaGetSymbolAddress((void**)&attn, g_attn);
    cudaGetSymbolAddress((void**)&res,  g_res);
    cudaGetSymbolAddress((void**)&ln,   g_ln);
    cudaGetSymbolAddress((void**)&hbuf, g_h);

    const size_t attn_smem = (size_t)(2 * 256 * KPAD + 8 * 64 + 8 * 256) * sizeof(float);
    cudaFuncSetAttribute(attn_kernel, cudaFuncAttributeMaxDynamicSharedMemorySize,
                         (int)attn_smem);

    dim3 blk(256);

    // 1) Q = x@Wq + bq
    sgemm_kernel<0, 0><<<dim3(DMODEL / 128, MQ / 128), blk>>>(
        MQ, DMODEL, DMODEL, x, Wq, bq, nullptr, nullptr, q);
    // 2) K = xf@Wk + bk ; 3) V = xf@Wv + bv
    sgemm_kernel<0, 0><<<dim3(DMODEL / 128, MKV / 128), blk>>>(
        MKV, DMODEL, DTEXT, xf, Wk, bk, nullptr, nullptr, k);
    sgemm_kernel<0, 0><<<dim3(DMODEL / 128, MKV / 128), blk>>>(
        MKV, DMODEL, DTEXT, xf, Wv, bv, nullptr, nullptr, v);
    // 4) attention
    attn_kernel<<<BDIM * NHEADS * (TXQ / QPB), blk, attn_smem>>>(q, k, v, attn);
    // 5) out = attn@Wo + bo  (residual base)
    sgemm_kernel<0, 0><<<dim3(DMODEL / 128, MQ / 128), blk>>>(
        MQ, DMODEL, DMODEL, attn, Wo, bo, nullptr, nullptr, res);
    // 6) ln = LayerNorm(out)
    ln_kernel<<<MQ, blk>>>(res, ln_g, ln_b, ln);
    // 7) h = GELU(ln@W1 + b1)
    sgemm_kernel<1, 0><<<dim3(DFF / 128, MQ / 128), blk>>>(
        MQ, DFF, DMODEL, ln, W1, b1, nullptr, nullptr, hbuf);
    // 8) final = h@W2 + b2 + out + x
    sgemm_kernel<0, 2><<<dim3(DMODEL / 128, MQ / 128), blk>>>(
        MQ, DMODEL, DFF, hbuf, W2, b2, res, x, out);
}

// round 4
// speedup vs baseline: 1.0007x; 1.0007x over previous
#include <cuda_runtime.h>
#include <math.h>

#define BDIM   4
#define TXQ    4096
#define TXFK   256
#define DMODEL 1024
#define DTEXT  768
#define NHEADS 16
#define HDIM   64
#define MQ     (BDIM*TXQ)     // 16384
#define MKV    (BDIM*TXFK)    // 1024
#define DFF    4096
#define ATT_SCALE 0.125f      // 64^-0.5

// ---------------- scratch (device globals; no allocation allowed) -------------
__device__ float g_q   [(size_t)MQ  * DMODEL];   // 64 MB
__device__ float g_k   [(size_t)MKV * DMODEL];   // 4 MB
__device__ float g_v   [(size_t)MKV * DMODEL];   // 4 MB
__device__ float g_attn[(size_t)MQ  * DMODEL];   // 64 MB
__device__ float g_res [(size_t)MQ  * DMODEL];   // out = attn@Wo+bo (residual base)
__device__ float g_ln  [(size_t)MQ  * DMODEL];   // LayerNorm(out)
__device__ float g_h   [(size_t)MQ  * DFF];      // GELU(ln@W1+b1), 256 MB

__device__ __forceinline__ float gelu_exact(float v) {
    return 0.5f * v * (1.0f + erff(v * 0.7071067811865476f));
}

// ---------------- generic fp32 SGEMM: C = act(A@W + bias) [+ res1 + res2] ----
// A: [M,K] row-major, W: [K,N] row-major, C: [M,N] row-major.
// BM=BN=128, BK=16, 256 threads, 8x8 per thread. All shapes divisible.
template<int ACT, int NRES>
__global__ void __launch_bounds__(256, 2) sgemm_kernel(
    int M, int N, int K,
    const float* __restrict__ A, const float* __restrict__ W,
    const float* __restrict__ bias,
    const float* __restrict__ res1, const float* __restrict__ res2,
    float* __restrict__ C)
{
    const int BM = 128, BN = 128, BK = 16;
    __shared__ float As[BK][BM];
    __shared__ float Bs[BK][BN];

    const int tid = threadIdx.x;
    const int tx  = tid & 15;        // 0..15 -> col block
    const int ty  = tid >> 4;        // 0..15 -> row block
    const int bx  = blockIdx.x;      // N tile
    const int by  = blockIdx.y;      // M tile

    // A load mapping: 128 rows x 16 cols -> 512 float4; 2 per thread
    const int a_row  = tid >> 2;          // 0..63 (also +64)
    const int a_col4 = (tid & 3) * 4;     // 0,4,8,12
    // W load mapping: 16 rows x 128 cols -> 512 float4; 2 per thread
    const int b_row  = tid >> 5;          // 0..7 (also +8)
    const int b_col4 = (tid & 31) * 4;    // 0..124

    const float* Ab = A + (size_t)by * BM * K;
    const float* Wb = W + (size_t)bx * BN;

    float acc[8][8];
#pragma unroll
    for (int i = 0; i < 8; i++)
#pragma unroll
        for (int j = 0; j < 8; j++) acc[i][j] = 0.0f;

    for (int k0 = 0; k0 < K; k0 += BK) {
        float4 a0 = *(const float4*)(Ab + (size_t)a_row        * K + k0 + a_col4);
        float4 a1 = *(const float4*)(Ab + (size_t)(a_row + 64) * K + k0 + a_col4);
        float4 w0 = *(const float4*)(Wb + (size_t)(k0 + b_row    ) * N + b_col4);
        float4 w1 = *(const float4*)(Wb + (size_t)(k0 + b_row + 8) * N + b_col4);

        As[a_col4 + 0][a_row     ] = a0.x;
        As[a_col4 + 1][a_row     ] = a0.y;
        As[a_col4 + 2][a_row     ] = a0.z;
        As[a_col4 + 3][a_row     ] = a0.w;
        As[a_col4 + 0][a_row + 64] = a1.x;
        As[a_col4 + 1][a_row + 64] = a1.y;
        As[a_col4 + 2][a_row + 64] = a1.z;
        As[a_col4 + 3][a_row + 64] = a1.w;
        *(float4*)&Bs[b_row    ][b_col4] = w0;
        *(float4*)&Bs[b_row + 8][b_col4] = w1;
        __syncthreads();

#pragma unroll
        for (int kk = 0; kk < BK; kk++) {
            float ra[8], rb[8];
            *(float4*)(ra    ) = *(const float4*)&As[kk][ty * 8    ];
            *(float4*)(ra + 4) = *(const float4*)&As[kk][ty * 8 + 4];
            *(float4*)(rb    ) = *(const float4*)&Bs[kk][tx * 8    ];
            *(float4*)(rb + 4) = *(const float4*)&Bs[kk][tx * 8 + 4];
#pragma unroll
            for (int i = 0; i < 8; i++)
#pragma unroll
                for (int j = 0; j < 8; j++)
                    acc[i][j] += ra[i] * rb[j];
        }
        __syncthreads();
    }

    const int row0 = by * BM + ty * 8;
    const int col0 = bx * BN + tx * 8;
#pragma unroll
    for (int i = 0; i < 8; i++) {
        size_t base = (size_t)(row0 + i) * N + col0;
        float4 o[2];
#pragma unroll
        for (int jj = 0; jj < 2; jj++) {
            float vv[4];
#pragma unroll
            for (int j = 0; j < 4; j++) {
                int jc = jj * 4 + j;
                float v = acc[i][jc] + bias[col0 + jc];
                if (ACT == 1) v = gelu_exact(v);
                if (NRES >= 1) v += res1[base + jc];
                if (NRES >= 2) v += res2[base + jc];
                vv[j] = v;
            }
            o[jj] = make_float4(vv[0], vv[1], vv[2], vv[3]);
        }
        *(float4*)(C + base)     = o[0];
        *(float4*)(C + base + 4) = o[1];
    }
}

// ---------------- attention: per (b, h, q-chunk) block ------------------------
// Q: [MQ, DMODEL] (head h occupies cols h*64..), K/V: [MKV, DMODEL].
// Whole 256x64 K and V head-tiles live in padded smem; softmax over all 256 keys.
#define QPB 256
#define KPAD 65

__global__ void __launch_bounds__(256) attn_kernel(
    const float* __restrict__ Q, const float* __restrict__ K,
    const float* __restrict__ V, float* __restrict__ O)
{
    extern __shared__ float sm[];
    float* Ks = sm;                  // 256*65
    float* Vs = Ks + 256 * KPAD;     // 256*65
    float* qs = Vs + 256 * KPAD;     // 8*64
    float* ps = qs + 8 * 64;         // 8*256

    const int nchunk = TXQ / QPB;    // 16
    const int bid   = blockIdx.x;
    const int chunk = bid % nchunk;
    const int h     = (bid / nchunk) % NHEADS;
    const int b     = bid / (nchunk * NHEADS);

    const int tid  = threadIdx.x;
    const int lane = tid & 31;
    const int w    = tid >> 5;

    // load K,V head tiles (256 rows x 64 cols) into padded smem
    for (int i = tid; i < 256 * 16; i += 256) {
        int j  = i >> 4;
        int dq = (i & 15) * 4;
        size_t gbase = (size_t)(b * TXFK + j) * DMODEL + h * HDIM + dq;
        float4 kv = *(const float4*)(K + gbase);
        float4 vv = *(const float4*)(V + gbase);
        Ks[j * KPAD + dq + 0] = kv.x; Ks[j * KPAD + dq + 1] = kv.y;
        Ks[j * KPAD + dq + 2] = kv.z; Ks[j * KPAD + dq + 3] = kv.w;
        Vs[j * KPAD + dq + 0] = vv.x; Vs[j * KPAD + dq + 1] = vv.y;
        Vs[j * KPAD + dq + 2] = vv.z; Vs[j * KPAD + dq + 3] = vv.w;
    }
    __syncthreads();

    for (int qi = 0; qi < 32; qi++) {
        const int qlocal = w * 32 + qi;
        const size_t qrow = (size_t)b * TXQ + (size_t)chunk * QPB + qlocal;
        const float* qp = Q + qrow * DMODEL + h * HDIM;
        qs[w * 64 + lane]      = qp[lane];
        qs[w * 64 + lane + 32] = qp[lane + 32];
        __syncwarp();

        // scores: lane owns keys j = lane + 32*c (conflict-free via KPAD=65)
        float s[8];
#pragma unroll
        for (int c = 0; c < 8; c++) s[c] = 0.0f;
        for (int d = 0; d < 64; d++) {
            float qd = qs[w * 64 + d];
#pragma unroll
            for (int c = 0; c < 8; c++)
                s[c] += qd * Ks[(lane + 32 * c) * KPAD + d];
        }
#pragma unroll
        for (int c = 0; c < 8; c++) s[c] *= ATT_SCALE;

        float mx = s[0];
#pragma unroll
        for (int c = 1; c < 8; c++) mx = fmaxf(mx, s[c]);
#pragma unroll
        for (int o = 16; o; o >>= 1) mx = fmaxf(mx, __shfl_xor_sync(~0u, mx, o));

        float sum = 0.0f;
#pragma unroll
        for (int c = 0; c < 8; c++) { s[c] = __expf(s[c] - mx); sum += s[c]; }
#pragma unroll
        for (int o = 16; o; o >>= 1) sum += __shfl_xor_sync(~0u, sum, o);
        float inv = 1.0f / sum;

#pragma unroll
        for (int c = 0; c < 8; c++) ps[w * 256 + lane + 32 * c] = s[c] * inv;
        __syncwarp();

        // output: lane owns dims d=lane and d=lane+32
        float o0 = 0.0f, o1 = 0.0f;
        for (int j = 0; j < 256; j++) {
            float p = ps[w * 256 + j];
            o0 += p * Vs[j * KPAD + lane];
            o1 += p * Vs[j * KPAD + lane + 32];
        }
        float* op = O + qrow * DMODEL + h * HDIM;
        op[lane]      = o0;
        op[lane + 32] = o1;
        __syncwarp();   // protect qs/ps reuse next iteration
    }
}

// ---------------- LayerNorm over rows of [MQ, 1024] ---------------------------
__global__ void __launch_bounds__(256) ln_kernel(
    const float* __restrict__ X, const float* __restrict__ gw,
    const float* __restrict__ bw, float* __restrict__ Y)
{
    const int row = blockIdx.x;
    const int t = threadIdx.x;
    float4 v = ((const float4*)(X + (size_t)row * DMODEL))[t];
    float s1 = v.x + v.y + v.z + v.w;
    float s2 = v.x * v.x + v.y * v.y + v.z * v.z + v.w * v.w;
#pragma unroll
    for (int o = 16; o; o >>= 1) {
        s1 += __shfl_xor_sync(~0u, s1, o);
        s2 += __shfl_xor_sync(~0u, s2, o);
    }
    __shared__ float r1[8], r2[8];
    const int w = t >> 5, lane = t & 31;
    if (lane == 0) { r1[w] = s1; r2[w] = s2; }
    __syncthreads();
    if (w == 0) {
        s1 = (lane < 8) ? r1[lane] : 0.0f;
        s2 = (lane < 8) ? r2[lane] : 0.0f;
#pragma unroll
        for (int o = 4; o; o >>= 1) {
            s1 += __shfl_xor_sync(~0u, s1, o);
            s2 += __shfl_xor_sync(~0u, s2, o);
        }
        if (lane == 0) { r1[0] = s1; r2[0] = s2; }
    }
    __syncthreads();
    const float mean = r1[0] * (1.0f / DMODEL);
    const float var  = r2[0] * (1.0f / DMODEL) - mean * mean;
    const float rstd = rsqrtf(var + 1e-5f);
    float4 g4 = ((const float4*)gw)[t];
    float4 b4 = ((const float4*)bw)[t];
    float4 o;
    o.x = (v.x - mean) * rstd * g4.x + b4.x;
    o.y = (v.y - mean) * rstd * g4.y + b4.y;
    o.z = (v.z - mean) * rstd * g4.z + b4.z;
    o.w = (v.w - mean) * rstd * g4.w + b4.w;
    ((float4*)(Y + (size_t)row * DMODEL))[t] = o;
}

// ---------------- launch -----------------------------------------------------
extern "C" void kernel_launch(void* const* d_in, const int* in_sizes, int n_in,
                              void* d_out, int out_size)
{
    const float* x    = (const float*)d_in[0];
    const float* xf   = (const float*)d_in[1];
    const float* Wq   = (const float*)d_in[2];
    const float* bq   = (const float*)d_in[3];
    const float* Wk   = (const float*)d_in[4];
    const float* bk   = (const float*)d_in[5];
    const float* Wv   = (const float*)d_in[6];
    const float* bv   = (const float*)d_in[7];
    const float* Wo   = (const float*)d_in[8];
    const float* bo   = (const float*)d_in[9];
    const float* ln_g = (const float*)d_in[10];
    const float* ln_b = (const float*)d_in[11];
    const float* W1   = (const float*)d_in[12];
    const float* b1   = (const float*)d_in[13];
    const float* W2   = (const float*)d_in[14];
    const float* b2   = (const float*)d_in[15];
    float* out = (float*)d_out;

    float *q, *k, *v, *attn, *res, *ln, *hbuf;
    cudaGetSymbolAddress((void**)&q,    g_q);
    cudaGetSymbolAddress((void**)&k,    g_k);
    cudaGetSymbolAddress((void**)&v,    g_v);
    cudaGetSymbolAddress((void**)&attn, g_attn);
    cudaGetSymbolAddress((void**)&res,  g_res);
    cudaGetSymbolAddress((void**)&ln,   g_ln);
    cudaGetSymbolAddress((void**)&hbuf, g_h);

    const size_t attn_smem = (size_t)(2 * 256 * KPAD + 8 * 64 + 8 * 256) * sizeof(float);
    cudaFuncSetAttribute(attn_kernel, cudaFuncAttributeMaxDynamicSharedMemorySize,
                         (int)attn_smem);

    dim3 blk(256);

    // 1) Q = x@Wq + bq
    sgemm_kernel<0, 0><<<dim3(DMODEL / 128, MQ / 128), blk>>>(
        MQ, DMODEL, DMODEL, x, Wq, bq, nullptr, nullptr, q);
    // 2) K = xf@Wk + bk ; 3) V = xf@Wv + bv
    sgemm_kernel<0, 0><<<dim3(DMODEL / 128, MKV / 128), blk>>>(
        MKV, DMODEL, DTEXT, xf, Wk, bk, nullptr, nullptr, k);
    sgemm_kernel<0, 0><<<dim3(DMODEL / 128, MKV / 128), blk>>>(
        MKV, DMODEL, DTEXT, xf, Wv, bv, nullptr, nullptr, v);
    // 4) attention
    attn_kernel<<<BDIM * NHEADS * (TXQ / QPB), blk, attn_smem>>>(q, k, v, attn);
    // 5) out = attn@Wo + bo  (residual base)
    sgemm_kernel<0, 0><<<dim3(DMODEL / 128, MQ / 128), blk>>>(
        MQ, DMODEL, DMODEL, attn, Wo, bo, nullptr, nullptr, res);
    // 6) ln = LayerNorm(out)
    ln_kernel<<<MQ, blk>>>(res, ln_g, ln_b, ln);
    // 7) h = GELU(ln@W1 + b1)
    sgemm_kernel<1, 0><<<dim3(DFF / 128, MQ / 128), blk>>>(
        MQ, DFF, DMODEL, ln, W1, b1, nullptr, nullptr, hbuf);
    // 8) final = h@W2 + b2 + out + x
    sgemm_kernel<0, 2><<<dim3(DMODEL / 128, MQ / 128), blk>>>(
        MQ, DMODEL, DFF, hbuf, W2, b2, res, x, out);
}

// round 6
// speedup vs baseline: 2.2445x; 2.2429x over previous
#include <cuda_runtime.h>
#include <cuda_bf16.h>
#include <math.h>
#include <stdint.h>

#define BDIM   4
#define TXQ    4096
#define TXFK   256
#define DMODEL 1024
#define DTEXT  768
#define NHEADS 16
#define HDIM   64
#define MQ     (BDIM*TXQ)     // 16384
#define MKV    (BDIM*TXFK)    // 1024
#define DFF    4096
#define ATT_SCALE 0.125f

// ---------------- scratch (device globals) -----------------------------------
__device__ float g_q   [(size_t)MQ  * DMODEL];
__device__ float g_k   [(size_t)MKV * DMODEL];
__device__ float g_v   [(size_t)MKV * DMODEL];
__device__ float g_attn[(size_t)MQ  * DMODEL];
__device__ float g_res [(size_t)MQ  * DMODEL];

// split-bf16: activations [hi | lo | hi], weights (transposed) [hi | hi | lo]
__device__ __nv_bfloat16 g_xs   [(size_t)MQ  * 3 * DMODEL];
__device__ __nv_bfloat16 g_xfs  [(size_t)MKV * 3 * DTEXT];
__device__ __nv_bfloat16 g_attns[(size_t)MQ  * 3 * DMODEL];
__device__ __nv_bfloat16 g_lns  [(size_t)MQ  * 3 * DMODEL];
__device__ __nv_bfloat16 g_hs   [(size_t)MQ  * 3 * DFF];
__device__ __nv_bfloat16 g_wq   [(size_t)DMODEL * 3 * DMODEL];
__device__ __nv_bfloat16 g_wk   [(size_t)DMODEL * 3 * DTEXT];
__device__ __nv_bfloat16 g_wv   [(size_t)DMODEL * 3 * DTEXT];
__device__ __nv_bfloat16 g_wo   [(size_t)DMODEL * 3 * DMODEL];
__device__ __nv_bfloat16 g_w1   [(size_t)DFF    * 3 * DMODEL];
__device__ __nv_bfloat16 g_w2   [(size_t)DMODEL * 3 * DFF];

__device__ __forceinline__ float gelu_exact(float v) {
    return 0.5f * v * (1.0f + erff(v * 0.7071067811865476f));
}

// ---------------- PTX helpers (all target-portable, sm_80+) -------------------
__device__ __forceinline__ uint32_t smem_u32(const void* p) {
    uint32_t a;
    asm("{ .reg .u64 t; cvta.to.shared.u64 t, %1; cvt.u32.u64 %0, t; }"
        : "=r"(a) : "l"(p));
    return a;
}
__device__ __forceinline__ void cp16(uint32_t s, const void* g) {
    asm volatile("cp.async.cg.shared.global [%0], [%1], 16;" :: "r"(s), "l"(g));
}
__device__ __forceinline__ void ldsm4(uint32_t* r, uint32_t a) {
    asm volatile("ldmatrix.sync.aligned.m8n8.x4.shared.b16 {%0,%1,%2,%3}, [%4];"
        : "=r"(r[0]), "=r"(r[1]), "=r"(r[2]), "=r"(r[3]) : "r"(a));
}
__device__ __forceinline__ void mma16816(float* c, const uint32_t* a,
                                         uint32_t b0, uint32_t b1) {
    asm volatile(
        "mma.sync.aligned.m16n8k16.row.col.f32.bf16.bf16.f32 "
        "{%0,%1,%2,%3}, {%4,%5,%6,%7}, {%8,%9}, {%0,%1,%2,%3};"
        : "+f"(c[0]), "+f"(c[1]), "+f"(c[2]), "+f"(c[3])
        : "r"(a[0]), "r"(a[1]), "r"(a[2]), "r"(a[3]), "r"(b0), "r"(b1));
}
__device__ __forceinline__ uint32_t pack_bf2(float a, float b) {
    __nv_bfloat162 t = __floats2bfloat162_rn(a, b);
    uint32_t u; memcpy(&u, &t, 4); return u;
}

// ---------------- bf16x3 HMMA GEMM --------------------------------------------
// C[M,N] = A'[M,Kp] @ B'[N,Kp]^T (Kp = 3*K_orig), BM=BN=128, BK=64.
// 256 threads = 8 warps, 4(M)x2(N) grid, warp tile 32x64.
// SMEM: A/B tiles 128 rows x 128B, swizzle chunk^(row&7) on 16B chunks.
// MODE 0: Cf = acc + bias
// MODE 2: split(gelu(acc + bias)) -> Cb [hi|lo|hi], row width 3*KOUT
// MODE 3: Cf = acc + bias + res1 + res2
#define STAGE_BYTES 32768       // 16KB A + 16KB B

template<int MODE>
__global__ void __launch_bounds__(256, 2) mma_gemm(
    int Nn, int Kp,
    const __nv_bfloat16* __restrict__ A, const __nv_bfloat16* __restrict__ Bw,
    const float* __restrict__ bias,
    const float* __restrict__ res1, const float* __restrict__ res2,
    float* __restrict__ Cf, __nv_bfloat16* __restrict__ Cb, int KOUT)
{
    extern __shared__ char smraw[];
    const uint32_t smb = smem_u32(smraw);

    const int tid = threadIdx.x;
    const int bx = blockIdx.x, by = blockIdx.y;
    const int w = tid >> 5, lane = tid & 31;
    const int m0w = (w & 3) * 32, n0w = (w >> 2) * 64;

    const __nv_bfloat16* Abase = A  + (size_t)(by * 128) * Kp;
    const __nv_bfloat16* Bbase = Bw + (size_t)(bx * 128) * Kp;
    const int nch = Kp >> 6;

    // per-thread load slots: 4 chunks for A, 4 for B (1024 chunks each / 256 thr)
    auto load_stage = [&](int c, int s) {
        const uint32_t sa = smb + s * STAGE_BYTES;
        const uint32_t sb = sa + 16384;
        const int k0 = c * 64;
#pragma unroll
        for (int i = 0; i < 4; i++) {
            int idx = tid + i * 256;
            int row = idx >> 3, cc = idx & 7;
            uint32_t off = row * 128 + ((cc ^ (row & 7)) << 4);
            cp16(sa + off, Abase + (size_t)row * Kp + k0 + cc * 8);
            cp16(sb + off, Bbase + (size_t)row * Kp + k0 + cc * 8);
        }
        asm volatile("cp.async.commit_group;" ::: "memory");
    };

    float acc[2][8][4];
#pragma unroll
    for (int i = 0; i < 2; i++)
#pragma unroll
        for (int j = 0; j < 8; j++)
#pragma unroll
            for (int q = 0; q < 4; q++) acc[i][j][q] = 0.0f;

    // precomputed ldmatrix lane addressing (offsets within a stage)
    const int a_row = m0w + (lane & 15);
    const int a_ccb = lane >> 4;                       // 0/1
    const int b_row = n0w + (lane & 7) + ((lane >> 4) << 3);
    const int b_ccb = (lane >> 3) & 1;                 // 0/1

    load_stage(0, 0);
    if (nch > 1) load_stage(1, 1);

    for (int c = 0; c < nch; c++) {
        const int s = c & 1;
        if (c + 1 < nch) asm volatile("cp.async.wait_group 1;" ::: "memory");
        else             asm volatile("cp.async.wait_group 0;" ::: "memory");
        __syncthreads();

        const uint32_t sa = smb + s * STAGE_BYTES;
        const uint32_t sb = sa + 16384;
#pragma unroll
        for (int kk = 0; kk < 4; kk++) {
            uint32_t af[2][4];
#pragma unroll
            for (int mi = 0; mi < 2; mi++) {
                int row = a_row + mi * 16;
                int cc = kk * 2 + a_ccb;
                ldsm4(af[mi], sa + row * 128 + ((cc ^ (row & 7)) << 4));
            }
#pragma unroll
            for (int nj = 0; nj < 4; nj++) {
                uint32_t bf[4];
                int row = b_row + nj * 16;
                int cc = kk * 2 + b_ccb;
                ldsm4(bf, sb + row * 128 + ((cc ^ (row & 7)) << 4));
#pragma unroll
                for (int mi = 0; mi < 2; mi++) {
                    mma16816(acc[mi][nj * 2],     af[mi], bf[0], bf[1]);
                    mma16816(acc[mi][nj * 2 + 1], af[mi], bf[2], bf[3]);
                }
            }
        }
        __syncthreads();
        if (c + 2 < nch) load_stage(c + 2, s);
    }

    // ---- epilogue from register accumulators
    const int g = lane >> 2, t = lane & 3;
#pragma unroll
    for (int mi = 0; mi < 2; mi++) {
#pragma unroll
        for (int ni = 0; ni < 8; ni++) {
            const int col = bx * 128 + n0w + ni * 8 + 2 * t;
            const float b0 = __ldg(bias + col);
            const float b1 = __ldg(bias + col + 1);
            const int row0 = by * 128 + m0w + mi * 16 + g;
#pragma unroll
            for (int h = 0; h < 2; h++) {
                const int row = row0 + h * 8;
                float v0 = acc[mi][ni][2 * h]     + b0;
                float v1 = acc[mi][ni][2 * h + 1] + b1;
                if (MODE == 2) {
                    v0 = gelu_exact(v0); v1 = gelu_exact(v1);
                    __nv_bfloat16 h0 = __float2bfloat16(v0);
                    __nv_bfloat16 h1 = __float2bfloat16(v1);
                    __nv_bfloat16 l0 = __float2bfloat16(v0 - __bfloat162float(h0));
                    __nv_bfloat16 l1 = __float2bfloat16(v1 - __bfloat162float(h1));
                    uint32_t hp = pack_bf2(__bfloat162float(h0), __bfloat162float(h1));
                    uint32_t lp = pack_bf2(__bfloat162float(l0), __bfloat162float(l1));
                    const size_t rb = (size_t)row * (3 * KOUT) + col;
                    *(uint32_t*)(Cb + rb)            = hp;
                    *(uint32_t*)(Cb + rb + KOUT)     = lp;
                    *(uint32_t*)(Cb + rb + 2 * KOUT) = hp;
                } else {
                    const size_t base = (size_t)row * Nn + col;
                    if (MODE == 3) {
                        v0 += res1[base]     + res2[base];
                        v1 += res1[base + 1] + res2[base + 1];
                    }
                    *(float2*)(Cf + base) = make_float2(v0, v1);
                }
            }
        }
    }
}

// ---------------- split conversions -------------------------------------------
__global__ void asplit_kernel(const float* __restrict__ X, __nv_bfloat16* __restrict__ Y,
                              int M, int K)
{
    size_t i = (size_t)blockIdx.x * blockDim.x + threadIdx.x;
    if (i >= (size_t)M * K) return;
    int m = (int)(i / K), k = (int)(i % K);
    float v = X[i];
    __nv_bfloat16 hi = __float2bfloat16(v);
    __nv_bfloat16 lo = __float2bfloat16(v - __bfloat162float(hi));
    size_t rb = (size_t)m * 3 * K;
    Y[rb + k] = hi; Y[rb + K + k] = lo; Y[rb + 2 * K + k] = hi;
}

__global__ void wsplit_kernel(const float* __restrict__ W, __nv_bfloat16* __restrict__ Y,
                              int K, int N)
{
    size_t i = (size_t)blockIdx.x * blockDim.x + threadIdx.x;
    if (i >= (size_t)K * N) return;
    int n = (int)(i / K), k = (int)(i % K);
    float v = W[(size_t)k * N + n];
    __nv_bfloat16 hi = __float2bfloat16(v);
    __nv_bfloat16 lo = __float2bfloat16(v - __bfloat162float(hi));
    size_t rb = (size_t)n * 3 * K;
    Y[rb + k] = hi; Y[rb + K + k] = hi; Y[rb + 2 * K + k] = lo;
}

// ---------------- attention ----------------------------------------------------
#define QPB 256
#define KPAD 65

__global__ void __launch_bounds__(256) attn_kernel(
    const float* __restrict__ Q, const float* __restrict__ K,
    const float* __restrict__ V, float* __restrict__ O)
{
    extern __shared__ float sm[];
    float* Ks = sm;
    float* Vs = Ks + 256 * KPAD;
    float* qs = Vs + 256 * KPAD;
    float* ps = qs + 8 * 64;

    const int nchunk = TXQ / QPB;
    const int bid   = blockIdx.x;
    const int chunk = bid % nchunk;
    const int h     = (bid / nchunk) % NHEADS;
    const int b     = bid / (nchunk * NHEADS);

    const int tid  = threadIdx.x;
    const int lane = tid & 31;
    const int w    = tid >> 5;

    for (int i = tid; i < 256 * 16; i += 256) {
        int j  = i >> 4;
        int dq = (i & 15) * 4;
        size_t gbase = (size_t)(b * TXFK + j) * DMODEL + h * HDIM + dq;
        float4 kv = *(const float4*)(K + gbase);
        float4 vv = *(const float4*)(V + gbase);
        Ks[j * KPAD + dq + 0] = kv.x; Ks[j * KPAD + dq + 1] = kv.y;
        Ks[j * KPAD + dq + 2] = kv.z; Ks[j * KPAD + dq + 3] = kv.w;
        Vs[j * KPAD + dq + 0] = vv.x; Vs[j * KPAD + dq + 1] = vv.y;
        Vs[j * KPAD + dq + 2] = vv.z; Vs[j * KPAD + dq + 3] = vv.w;
    }
    __syncthreads();

    for (int qi = 0; qi < 32; qi++) {
        const int qlocal = w * 32 + qi;
        const size_t qrow = (size_t)b * TXQ + (size_t)chunk * QPB + qlocal;
        const float* qp = Q + qrow * DMODEL + h * HDIM;
        qs[w * 64 + lane]      = qp[lane];
        qs[w * 64 + lane + 32] = qp[lane + 32];
        __syncwarp();

        float s[8];
#pragma unroll
        for (int c = 0; c < 8; c++) s[c] = 0.0f;
        for (int d = 0; d < 64; d++) {
            float qd = qs[w * 64 + d];
#pragma unroll
            for (int c = 0; c < 8; c++)
                s[c] += qd * Ks[(lane + 32 * c) * KPAD + d];
        }
#pragma unroll
        for (int c = 0; c < 8; c++) s[c] *= ATT_SCALE;

        float mx = s[0];
#pragma unroll
        for (int c = 1; c < 8; c++) mx = fmaxf(mx, s[c]);
#pragma unroll
        for (int o = 16; o; o >>= 1) mx = fmaxf(mx, __shfl_xor_sync(~0u, mx, o));

        float sum = 0.0f;
#pragma unroll
        for (int c = 0; c < 8; c++) { s[c] = __expf(s[c] - mx); sum += s[c]; }
#pragma unroll
        for (int o = 16; o; o >>= 1) sum += __shfl_xor_sync(~0u, sum, o);
        float inv = 1.0f / sum;

#pragma unroll
        for (int c = 0; c < 8; c++) ps[w * 256 + lane + 32 * c] = s[c] * inv;
        __syncwarp();

        float o0 = 0.0f, o1 = 0.0f;
        for (int j = 0; j < 256; j++) {
            float p = ps[w * 256 + j];
            o0 += p * Vs[j * KPAD + lane];
            o1 += p * Vs[j * KPAD + lane + 32];
        }
        float* op = O + qrow * DMODEL + h * HDIM;
        op[lane]      = o0;
        op[lane + 32] = o1;
        __syncwarp();
    }
}

// ---------------- LayerNorm -> split bf16 --------------------------------------
__global__ void __launch_bounds__(256) ln_split_kernel(
    const float* __restrict__ X, const float* __restrict__ gw,
    const float* __restrict__ bw, __nv_bfloat16* __restrict__ Y)
{
    const int row = blockIdx.x;
    const int t = threadIdx.x;
    float4 v = ((const float4*)(X + (size_t)row * DMODEL))[t];
    float s1 = v.x + v.y + v.z + v.w;
    float s2 = v.x * v.x + v.y * v.y + v.z * v.z + v.w * v.w;
#pragma unroll
    for (int o = 16; o; o >>= 1) {
        s1 += __shfl_xor_sync(~0u, s1, o);
        s2 += __shfl_xor_sync(~0u, s2, o);
    }
    __shared__ float r1[8], r2[8];
    const int w = t >> 5, lane = t & 31;
    if (lane == 0) { r1[w] = s1; r2[w] = s2; }
    __syncthreads();
    if (w == 0) {
        s1 = (lane < 8) ? r1[lane] : 0.0f;
        s2 = (lane < 8) ? r2[lane] : 0.0f;
#pragma unroll
        for (int o = 4; o; o >>= 1) {
            s1 += __shfl_xor_sync(~0u, s1, o);
            s2 += __shfl_xor_sync(~0u, s2, o);
        }
        if (lane == 0) { r1[0] = s1; r2[0] = s2; }
    }
    __syncthreads();
    const float mean = r1[0] * (1.0f / DMODEL);
    const float var  = r2[0] * (1.0f / DMODEL) - mean * mean;
    const float rstd = rsqrtf(var + 1e-5f);
    float4 g4 = ((const float4*)gw)[t];
    float4 b4 = ((const float4*)bw)[t];
    float vv[4];
    vv[0] = (v.x - mean) * rstd * g4.x + b4.x;
    vv[1] = (v.y - mean) * rstd * g4.y + b4.y;
    vv[2] = (v.z - mean) * rstd * g4.z + b4.z;
    vv[3] = (v.w - mean) * rstd * g4.w + b4.w;

    const size_t rb = (size_t)row * 3 * DMODEL;
    const int c = t * 4;
    uint32_t hp[2], lp[2];
#pragma unroll
    for (int jj = 0; jj < 2; jj++) {
        __nv_bfloat16 h0 = __float2bfloat16(vv[2*jj]);
        __nv_bfloat16 h1 = __float2bfloat16(vv[2*jj+1]);
        __nv_bfloat16 l0 = __float2bfloat16(vv[2*jj]   - __bfloat162float(h0));
        __nv_bfloat16 l1 = __float2bfloat16(vv[2*jj+1] - __bfloat162float(h1));
        hp[jj] = pack_bf2(__bfloat162float(h0), __bfloat162float(h1));
        lp[jj] = pack_bf2(__bfloat162float(l0), __bfloat162float(l1));
    }
    *(uint2*)(Y + rb + c)              = make_uint2(hp[0], hp[1]);
    *(uint2*)(Y + rb + DMODEL + c)     = make_uint2(lp[0], lp[1]);
    *(uint2*)(Y + rb + 2 * DMODEL + c) = make_uint2(hp[0], hp[1]);
}

// ---------------- launch -------------------------------------------------------
extern "C" void kernel_launch(void* const* d_in, const int* in_sizes, int n_in,
                              void* d_out, int out_size)
{
    const float* x    = (const float*)d_in[0];
    const float* xf   = (const float*)d_in[1];
    const float* Wq   = (const float*)d_in[2];
    const float* bq   = (const float*)d_in[3];
    const float* Wk   = (const float*)d_in[4];
    const float* bk   = (const float*)d_in[5];
    const float* Wv   = (const float*)d_in[6];
    const float* bv   = (const float*)d_in[7];
    const float* Wo   = (const float*)d_in[8];
    const float* bo   = (const float*)d_in[9];
    const float* ln_g = (const float*)d_in[10];
    const float* ln_b = (const float*)d_in[11];
    const float* W1   = (const float*)d_in[12];
    const float* b1   = (const float*)d_in[13];
    const float* W2   = (const float*)d_in[14];
    const float* b2   = (const float*)d_in[15];
    float* out = (float*)d_out;

    float *q, *k, *v, *attn, *res;
    __nv_bfloat16 *xs, *xfs, *attns, *lns, *hs, *wq, *wk, *wv, *wo, *w1, *w2;
    cudaGetSymbolAddress((void**)&q,     g_q);
    cudaGetSymbolAddress((void**)&k,     g_k);
    cudaGetSymbolAddress((void**)&v,     g_v);
    cudaGetSymbolAddress((void**)&attn,  g_attn);
    cudaGetSymbolAddress((void**)&res,   g_res);
    cudaGetSymbolAddress((void**)&xs,    g_xs);
    cudaGetSymbolAddress((void**)&xfs,   g_xfs);
    cudaGetSymbolAddress((void**)&attns, g_attns);
    cudaGetSymbolAddress((void**)&lns,   g_lns);
    cudaGetSymbolAddress((void**)&hs,    g_hs);
    cudaGetSymbolAddress((void**)&wq,    g_wq);
    cudaGetSymbolAddress((void**)&wk,    g_wk);
    cudaGetSymbolAddress((void**)&wv,    g_wv);
    cudaGetSymbolAddress((void**)&wo,    g_wo);
    cudaGetSymbolAddress((void**)&w1,    g_w1);
    cudaGetSymbolAddress((void**)&w2,    g_w2);

    const int GEMM_SMEM = 2 * STAGE_BYTES;   // 64KB
    cudaFuncSetAttribute(mma_gemm<0>, cudaFuncAttributeMaxDynamicSharedMemorySize, GEMM_SMEM);
    cudaFuncSetAttribute(mma_gemm<2>, cudaFuncAttributeMaxDynamicSharedMemorySize, GEMM_SMEM);
    cudaFuncSetAttribute(mma_gemm<3>, cudaFuncAttributeMaxDynamicSharedMemorySize, GEMM_SMEM);
    const size_t attn_smem = (size_t)(2 * 256 * KPAD + 8 * 64 + 8 * 256) * sizeof(float);
    cudaFuncSetAttribute(attn_kernel, cudaFuncAttributeMaxDynamicSharedMemorySize,
                         (int)attn_smem);

    dim3 blk(256);
    auto cdiv = [](size_t a, size_t b) { return (unsigned)((a + b - 1) / b); };

    // weight transposition + splits
    wsplit_kernel<<<cdiv((size_t)DMODEL * DMODEL, 256), blk>>>(Wq, wq, DMODEL, DMODEL);
    wsplit_kernel<<<cdiv((size_t)DTEXT  * DMODEL, 256), blk>>>(Wk, wk, DTEXT,  DMODEL);
    wsplit_kernel<<<cdiv((size_t)DTEXT  * DMODEL, 256), blk>>>(Wv, wv, DTEXT,  DMODEL);
    wsplit_kernel<<<cdiv((size_t)DMODEL * DMODEL, 256), blk>>>(Wo, wo, DMODEL, DMODEL);
    wsplit_kernel<<<cdiv((size_t)DMODEL * DFF,    256), blk>>>(W1, w1, DMODEL, DFF);
    wsplit_kernel<<<cdiv((size_t)DFF    * DMODEL, 256), blk>>>(W2, w2, DFF,    DMODEL);
    // activation splits
    asplit_kernel<<<cdiv((size_t)MQ  * DMODEL, 256), blk>>>(x,  xs,  MQ,  DMODEL);
    asplit_kernel<<<cdiv((size_t)MKV * DTEXT,  256), blk>>>(xf, xfs, MKV, DTEXT);

    // Q = x@Wq + bq ; K/V = xf@W{k,v} + b
    mma_gemm<0><<<dim3(DMODEL / 128, MQ / 128), blk, GEMM_SMEM>>>(
        DMODEL, 3 * DMODEL, xs, wq, bq, nullptr, nullptr, q, nullptr, 0);
    mma_gemm<0><<<dim3(DMODEL / 128, MKV / 128), blk, GEMM_SMEM>>>(
        DMODEL, 3 * DTEXT, xfs, wk, bk, nullptr, nullptr, k, nullptr, 0);
    mma_gemm<0><<<dim3(DMODEL / 128, MKV / 128), blk, GEMM_SMEM>>>(
        DMODEL, 3 * DTEXT, xfs, wv, bv, nullptr, nullptr, v, nullptr, 0);

    // attention
    attn_kernel<<<BDIM * NHEADS * (TXQ / QPB), blk, attn_smem>>>(q, k, v, attn);
    asplit_kernel<<<cdiv((size_t)MQ * DMODEL, 256), blk>>>(attn, attns, MQ, DMODEL);

    // out = attn@Wo + bo (residual base)
    mma_gemm<0><<<dim3(DMODEL / 128, MQ / 128), blk, GEMM_SMEM>>>(
        DMODEL, 3 * DMODEL, attns, wo, bo, nullptr, nullptr, res, nullptr, 0);

    // LayerNorm -> split
    ln_split_kernel<<<MQ, blk>>>(res, ln_g, ln_b, lns);

    // h = GELU(ln@W1 + b1) -> split directly
    mma_gemm<2><<<dim3(DFF / 128, MQ / 128), blk, GEMM_SMEM>>>(
        DFF, 3 * DMODEL, lns, w1, b1, nullptr, nullptr, nullptr, hs, DFF);

    // final = h@W2 + b2 + res + x
    mma_gemm<3><<<dim3(DMODEL / 128, MQ / 128), blk, GEMM_SMEM>>>(
        DMODEL, 3 * DFF, hs, w2, b2, res, x, out, nullptr, 0);
}

// round 7
// speedup vs baseline: 2.5296x; 1.1270x over previous
#include <cuda_runtime.h>
#include <cuda_bf16.h>
#include <math.h>
#include <stdint.h>

#define BDIM   4
#define TXQ    4096
#define TXFK   256
#define DMODEL 1024
#define DTEXT  768
#define NHEADS 16
#define HDIM   64
#define MQ     (BDIM*TXQ)     // 16384
#define MKV    (BDIM*TXFK)    // 1024
#define DFF    4096
#define ATT_SCALE 0.125f

// ---------------- scratch (device globals) -----------------------------------
__device__ float g_q   [(size_t)MQ  * DMODEL];
__device__ float g_k   [(size_t)MKV * DMODEL];
__device__ float g_v   [(size_t)MKV * DMODEL];
__device__ float g_attn[(size_t)MQ  * DMODEL];
__device__ float g_res [(size_t)MQ  * DMODEL];

// split-bf16: activations [hi | lo | hi], weights (transposed) [hi | hi | lo]
__device__ __nv_bfloat16 g_xs   [(size_t)MQ  * 3 * DMODEL];
__device__ __nv_bfloat16 g_xfs  [(size_t)MKV * 3 * DTEXT];
__device__ __nv_bfloat16 g_attns[(size_t)MQ  * 3 * DMODEL];
__device__ __nv_bfloat16 g_lns  [(size_t)MQ  * 3 * DMODEL];
__device__ __nv_bfloat16 g_hs   [(size_t)MQ  * 3 * DFF];
__device__ __nv_bfloat16 g_wq   [(size_t)DMODEL * 3 * DMODEL];
__device__ __nv_bfloat16 g_wk   [(size_t)DMODEL * 3 * DTEXT];
__device__ __nv_bfloat16 g_wv   [(size_t)DMODEL * 3 * DTEXT];
__device__ __nv_bfloat16 g_wo   [(size_t)DMODEL * 3 * DMODEL];
__device__ __nv_bfloat16 g_w1   [(size_t)DFF    * 3 * DMODEL];
__device__ __nv_bfloat16 g_w2   [(size_t)DMODEL * 3 * DFF];

__device__ __forceinline__ float gelu_exact(float v) {
    return 0.5f * v * (1.0f + erff(v * 0.7071067811865476f));
}

// ---------------- PTX helpers (target-portable, sm_80+) -----------------------
__device__ __forceinline__ uint32_t smem_u32(const void* p) {
    uint32_t a;
    asm("{ .reg .u64 t; cvta.to.shared.u64 t, %1; cvt.u32.u64 %0, t; }"
        : "=r"(a) : "l"(p));
    return a;
}
__device__ __forceinline__ void cp16(uint32_t s, const void* g) {
    asm volatile("cp.async.cg.shared.global [%0], [%1], 16;" :: "r"(s), "l"(g));
}
__device__ __forceinline__ void ldsm4(uint32_t* r, uint32_t a) {
    asm volatile("ldmatrix.sync.aligned.m8n8.x4.shared.b16 {%0,%1,%2,%3}, [%4];"
        : "=r"(r[0]), "=r"(r[1]), "=r"(r[2]), "=r"(r[3]) : "r"(a));
}
__device__ __forceinline__ void mma16816(float* c, const uint32_t* a,
                                         uint32_t b0, uint32_t b1) {
    asm volatile(
        "mma.sync.aligned.m16n8k16.row.col.f32.bf16.bf16.f32 "
        "{%0,%1,%2,%3}, {%4,%5,%6,%7}, {%8,%9}, {%0,%1,%2,%3};"
        : "+f"(c[0]), "+f"(c[1]), "+f"(c[2]), "+f"(c[3])
        : "r"(a[0]), "r"(a[1]), "r"(a[2]), "r"(a[3]), "r"(b0), "r"(b1));
}
__device__ __forceinline__ uint32_t pack_bf2(float a, float b) {
    __nv_bfloat162 t = __floats2bfloat162_rn(a, b);
    uint32_t u; memcpy(&u, &t, 4); return u;
}

// ---------------- bf16x3 HMMA GEMM --------------------------------------------
// C[M,N] = A'[M,Kp] @ B'[N,Kp]^T (Kp = 3*K_orig), BM=BN=128, BK=64.
// 256 threads = 8 warps, 4(M)x2(N) grid, warp tile 32x64.
// 3-stage cp.async pipeline, one barrier/iter. L2-friendly CTA swizzle (G=16).
// MODE 0: Cf = acc + bias
// MODE 2: split(gelu(acc + bias)) -> Cb [hi|lo|hi], row width 3*KOUT
// MODE 3: Cf = acc + bias + res1 + res2
#define STAGE_BYTES 32768       // 16KB A + 16KB B
#define NSTAGE 3
#define RASTER_G 16

template<int MODE>
__global__ void __launch_bounds__(256, 2) mma_gemm(
    int Nn, int Kp,
    const __nv_bfloat16* __restrict__ A, const __nv_bfloat16* __restrict__ Bw,
    const float* __restrict__ bias,
    const float* __restrict__ res1, const float* __restrict__ res2,
    float* __restrict__ Cf, __nv_bfloat16* __restrict__ Cb, int KOUT)
{
    extern __shared__ char smraw[];
    const uint32_t smb = smem_u32(smraw);

    const int tid = threadIdx.x;
    // ---- L2-aware rasterization: strips of RASTER_G rows, column-major inside
    const int numX = gridDim.x, numY = gridDim.y;
    const int bid = blockIdx.y * numX + blockIdx.x;
    const int strip = RASTER_G * numX;
    const int sIdx = bid / strip;
    const int rIdx = bid % strip;
    const int gRows = (numY - sIdx * RASTER_G) < RASTER_G ? (numY - sIdx * RASTER_G)
                                                          : RASTER_G;
    const int by = sIdx * RASTER_G + (rIdx % gRows);
    const int bx = rIdx / gRows;

    const int w = tid >> 5, lane = tid & 31;
    const int m0w = (w & 3) * 32, n0w = (w >> 2) * 64;

    const __nv_bfloat16* Abase = A  + (size_t)(by * 128) * Kp;
    const __nv_bfloat16* Bbase = Bw + (size_t)(bx * 128) * Kp;
    const int nch = Kp >> 6;

    auto load_stage = [&](int c, int s) {
        const uint32_t sa = smb + s * STAGE_BYTES;
        const uint32_t sb = sa + 16384;
        const int k0 = c * 64;
#pragma unroll
        for (int i = 0; i < 4; i++) {
            int idx = tid + i * 256;
            int row = idx >> 3, cc = idx & 7;
            uint32_t off = row * 128 + ((cc ^ (row & 7)) << 4);
            cp16(sa + off, Abase + (size_t)row * Kp + k0 + cc * 8);
            cp16(sb + off, Bbase + (size_t)row * Kp + k0 + cc * 8);
        }
        asm volatile("cp.async.commit_group;" ::: "memory");
    };

    float acc[2][8][4];
#pragma unroll
    for (int i = 0; i < 2; i++)
#pragma unroll
        for (int j = 0; j < 8; j++)
#pragma unroll
            for (int q = 0; q < 4; q++) acc[i][j][q] = 0.0f;

    const int a_row = m0w + (lane & 15);
    const int a_ccb = lane >> 4;
    const int b_row = n0w + (lane & 7) + ((lane >> 4) << 3);
    const int b_ccb = (lane >> 3) & 1;

    load_stage(0, 0);
    if (nch > 1) load_stage(1, 1);

    for (int c = 0; c < nch; c++) {
        const int s = c % NSTAGE;
        if (c + 1 < nch) asm volatile("cp.async.wait_group 1;" ::: "memory");
        else             asm volatile("cp.async.wait_group 0;" ::: "memory");
        __syncthreads();
        if (c + 2 < nch) load_stage(c + 2, (c + 2) % NSTAGE);

        const uint32_t sa = smb + s * STAGE_BYTES;
        const uint32_t sb = sa + 16384;
#pragma unroll
        for (int kk = 0; kk < 4; kk++) {
            uint32_t af[2][4];
#pragma unroll
            for (int mi = 0; mi < 2; mi++) {
                int row = a_row + mi * 16;
                int cc = kk * 2 + a_ccb;
                ldsm4(af[mi], sa + row * 128 + ((cc ^ (row & 7)) << 4));
            }
#pragma unroll
            for (int nj = 0; nj < 4; nj++) {
                uint32_t bf[4];
                int row = b_row + nj * 16;
                int cc = kk * 2 + b_ccb;
                ldsm4(bf, sb + row * 128 + ((cc ^ (row & 7)) << 4));
#pragma unroll
                for (int mi = 0; mi < 2; mi++) {
                    mma16816(acc[mi][nj * 2],     af[mi], bf[0], bf[1]);
                    mma16816(acc[mi][nj * 2 + 1], af[mi], bf[2], bf[3]);
                }
            }
        }
    }

    // ---- epilogue from register accumulators
    const int g = lane >> 2, t = lane & 3;
#pragma unroll
    for (int mi = 0; mi < 2; mi++) {
#pragma unroll
        for (int ni = 0; ni < 8; ni++) {
            const int col = bx * 128 + n0w + ni * 8 + 2 * t;
            const float b0 = __ldg(bias + col);
            const float b1 = __ldg(bias + col + 1);
            const int row0 = by * 128 + m0w + mi * 16 + g;
#pragma unroll
            for (int h = 0; h < 2; h++) {
                const int row = row0 + h * 8;
                float v0 = acc[mi][ni][2 * h]     + b0;
                float v1 = acc[mi][ni][2 * h + 1] + b1;
                if (MODE == 2) {
                    v0 = gelu_exact(v0); v1 = gelu_exact(v1);
                    __nv_bfloat16 h0 = __float2bfloat16(v0);
                    __nv_bfloat16 h1 = __float2bfloat16(v1);
                    __nv_bfloat16 l0 = __float2bfloat16(v0 - __bfloat162float(h0));
                    __nv_bfloat16 l1 = __float2bfloat16(v1 - __bfloat162float(h1));
                    uint32_t hp = pack_bf2(__bfloat162float(h0), __bfloat162float(h1));
                    uint32_t lp = pack_bf2(__bfloat162float(l0), __bfloat162float(l1));
                    const size_t rb = (size_t)row * (3 * KOUT) + col;
                    *(uint32_t*)(Cb + rb)            = hp;
                    *(uint32_t*)(Cb + rb + KOUT)     = lp;
                    *(uint32_t*)(Cb + rb + 2 * KOUT) = hp;
                } else {
                    const size_t base = (size_t)row * Nn + col;
                    if (MODE == 3) {
                        v0 += res1[base]     + res2[base];
                        v1 += res1[base + 1] + res2[base + 1];
                    }
                    *(float2*)(Cf + base) = make_float2(v0, v1);
                }
            }
        }
    }
}

// ---------------- split conversions -------------------------------------------
__global__ void asplit_kernel(const float* __restrict__ X, __nv_bfloat16* __restrict__ Y,
                              int M, int K)
{
    size_t i = (size_t)blockIdx.x * blockDim.x + threadIdx.x;
    if (i >= (size_t)M * K) return;
    int m = (int)(i / K), k = (int)(i % K);
    float v = X[i];
    __nv_bfloat16 hi = __float2bfloat16(v);
    __nv_bfloat16 lo = __float2bfloat16(v - __bfloat162float(hi));
    size_t rb = (size_t)m * 3 * K;
    Y[rb + k] = hi; Y[rb + K + k] = lo; Y[rb + 2 * K + k] = hi;
}

__global__ void wsplit_kernel(const float* __restrict__ W, __nv_bfloat16* __restrict__ Y,
                              int K, int N)
{
    size_t i = (size_t)blockIdx.x * blockDim.x + threadIdx.x;
    if (i >= (size_t)K * N) return;
    int n = (int)(i / K), k = (int)(i % K);
    float v = W[(size_t)k * N + n];
    __nv_bfloat16 hi = __float2bfloat16(v);
    __nv_bfloat16 lo = __float2bfloat16(v - __bfloat162float(hi));
    size_t rb = (size_t)n * 3 * K;
    Y[rb + k] = hi; Y[rb + K + k] = hi; Y[rb + 2 * K + k] = lo;
}

// ---------------- attention: 4 queries per warp-iteration ----------------------
#define QPB 256
#define KPAD 65

__global__ void __launch_bounds__(256) attn_kernel(
    const float* __restrict__ Q, const float* __restrict__ K,
    const float* __restrict__ V, float* __restrict__ O)
{
    extern __shared__ float sm[];
    float* Ks = sm;                      // 256*65
    float* Vs = Ks + 256 * KPAD;         // 256*65
    float* qs = Vs + 256 * KPAD;         // 8 warps * 4 q * 64
    float* ps = qs + 8 * 4 * 64;         // 8 warps * 4 q * 256

    const int nchunk = TXQ / QPB;
    const int bid   = blockIdx.x;
    const int chunk = bid % nchunk;
    const int h     = (bid / nchunk) % NHEADS;
    const int b     = bid / (nchunk * NHEADS);

    const int tid  = threadIdx.x;
    const int lane = tid & 31;
    const int w    = tid >> 5;

    for (int i = tid; i < 256 * 16; i += 256) {
        int j  = i >> 4;
        int dq = (i & 15) * 4;
        size_t gbase = (size_t)(b * TXFK + j) * DMODEL + h * HDIM + dq;
        float4 kv = *(const float4*)(K + gbase);
        float4 vv = *(const float4*)(V + gbase);
        Ks[j * KPAD + dq + 0] = kv.x; Ks[j * KPAD + dq + 1] = kv.y;
        Ks[j * KPAD + dq + 2] = kv.z; Ks[j * KPAD + dq + 3] = kv.w;
        Vs[j * KPAD + dq + 0] = vv.x; Vs[j * KPAD + dq + 1] = vv.y;
        Vs[j * KPAD + dq + 2] = vv.z; Vs[j * KPAD + dq + 3] = vv.w;
    }
    __syncthreads();

    float* qw = qs + w * 4 * 64;
    float* pw = ps + w * 4 * 256;

    for (int qt = 0; qt < 8; qt++) {
        const size_t qrow0 = (size_t)b * TXQ + (size_t)chunk * QPB + w * 32 + qt * 4;
        // load 4 query rows into per-warp smem
#pragma unroll
        for (int r = 0; r < 4; r++) {
            const float* qp = Q + (qrow0 + r) * DMODEL + h * HDIM;
            qw[r * 64 + lane]      = qp[lane];
            qw[r * 64 + lane + 32] = qp[lane + 32];
        }
        __syncwarp();

        // scores: lane owns keys j = lane + 32*c for 4 queries
        float s[4][8];
#pragma unroll
        for (int r = 0; r < 4; r++)
#pragma unroll
            for (int c = 0; c < 8; c++) s[r][c] = 0.0f;

        for (int d = 0; d < 64; d++) {
            float kv[8];
#pragma unroll
            for (int c = 0; c < 8; c++) kv[c] = Ks[(lane + 32 * c) * KPAD + d];
            float qd[4];
#pragma unroll
            for (int r = 0; r < 4; r++) qd[r] = qw[r * 64 + d];
#pragma unroll
            for (int r = 0; r < 4; r++)
#pragma unroll
                for (int c = 0; c < 8; c++) s[r][c] += qd[r] * kv[c];
        }

#pragma unroll
        for (int r = 0; r < 4; r++) {
#pragma unroll
            for (int c = 0; c < 8; c++) s[r][c] *= ATT_SCALE;
            float mx = s[r][0];
#pragma unroll
            for (int c = 1; c < 8; c++) mx = fmaxf(mx, s[r][c]);
#pragma unroll
            for (int o = 16; o; o >>= 1) mx = fmaxf(mx, __shfl_xor_sync(~0u, mx, o));
            float sum = 0.0f;
#pragma unroll
            for (int c = 0; c < 8; c++) { s[r][c] = __expf(s[r][c] - mx); sum += s[r][c]; }
#pragma unroll
            for (int o = 16; o; o >>= 1) sum += __shfl_xor_sync(~0u, sum, o);
            float inv = 1.0f / sum;
#pragma unroll
            for (int c = 0; c < 8; c++) pw[r * 256 + lane + 32 * c] = s[r][c] * inv;
        }
        __syncwarp();

        // output: lane owns dims d=lane and d=lane+32 for 4 queries
        float o0[4], o1[4];
#pragma unroll
        for (int r = 0; r < 4; r++) { o0[r] = 0.0f; o1[r] = 0.0f; }
        for (int j = 0; j < 256; j += 2) {
            float va0 = Vs[j * KPAD + lane];
            float va1 = Vs[j * KPAD + lane + 32];
            float vb0 = Vs[(j + 1) * KPAD + lane];
            float vb1 = Vs[(j + 1) * KPAD + lane + 32];
#pragma unroll
            for (int r = 0; r < 4; r++) {
                float pa = pw[r * 256 + j];
                float pb = pw[r * 256 + j + 1];
                o0[r] += pa * va0 + pb * vb0;
                o1[r] += pa * va1 + pb * vb1;
            }
        }
#pragma unroll
        for (int r = 0; r < 4; r++) {
            float* op = O + (qrow0 + r) * DMODEL + h * HDIM;
            op[lane]      = o0[r];
            op[lane + 32] = o1[r];
        }
        __syncwarp();
    }
}

// ---------------- LayerNorm -> split bf16 --------------------------------------
__global__ void __launch_bounds__(256) ln_split_kernel(
    const float* __restrict__ X, const float* __restrict__ gw,
    const float* __restrict__ bw, __nv_bfloat16* __restrict__ Y)
{
    const int row = blockIdx.x;
    const int t = threadIdx.x;
    float4 v = ((const float4*)(X + (size_t)row * DMODEL))[t];
    float s1 = v.x + v.y + v.z + v.w;
    float s2 = v.x * v.x + v.y * v.y + v.z * v.z + v.w * v.w;
#pragma unroll
    for (int o = 16; o; o >>= 1) {
        s1 += __shfl_xor_sync(~0u, s1, o);
        s2 += __shfl_xor_sync(~0u, s2, o);
    }
    __shared__ float r1[8], r2[8];
    const int w = t >> 5, lane = t & 31;
    if (lane == 0) { r1[w] = s1; r2[w] = s2; }
    __syncthreads();
    if (w == 0) {
        s1 = (lane < 8) ? r1[lane] : 0.0f;
        s2 = (lane < 8) ? r2[lane] : 0.0f;
#pragma unroll
        for (int o = 4; o; o >>= 1) {
            s1 += __shfl_xor_sync(~0u, s1, o);
            s2 += __shfl_xor_sync(~0u, s2, o);
        }
        if (lane == 0) { r1[0] = s1; r2[0] = s2; }
    }
    __syncthreads();
    const float mean = r1[0] * (1.0f / DMODEL);
    const float var  = r2[0] * (1.0f / DMODEL) - mean * mean;
    const float rstd = rsqrtf(var + 1e-5f);
    float4 g4 = ((const float4*)gw)[t];
    float4 b4 = ((const float4*)bw)[t];
    float vv[4];
    vv[0] = (v.x - mean) * rstd * g4.x + b4.x;
    vv[1] = (v.y - mean) * rstd * g4.y + b4.y;
    vv[2] = (v.z - mean) * rstd * g4.z + b4.z;
    vv[3] = (v.w - mean) * rstd * g4.w + b4.w;

    const size_t rb = (size_t)row * 3 * DMODEL;
    const int c = t * 4;
    uint32_t hp[2], lp[2];
#pragma unroll
    for (int jj = 0; jj < 2; jj++) {
        __nv_bfloat16 h0 = __float2bfloat16(vv[2*jj]);
        __nv_bfloat16 h1 = __float2bfloat16(vv[2*jj+1]);
        __nv_bfloat16 l0 = __float2bfloat16(vv[2*jj]   - __bfloat162float(h0));
        __nv_bfloat16 l1 = __float2bfloat16(vv[2*jj+1] - __bfloat162float(h1));
        hp[jj] = pack_bf2(__bfloat162float(h0), __bfloat162float(h1));
        lp[jj] = pack_bf2(__bfloat162float(l0), __bfloat162float(l1));
    }
    *(uint2*)(Y + rb + c)              = make_uint2(hp[0], hp[1]);
    *(uint2*)(Y + rb + DMODEL + c)     = make_uint2(lp[0], lp[1]);
    *(uint2*)(Y + rb + 2 * DMODEL + c) = make_uint2(hp[0], hp[1]);
}

// ---------------- launch -------------------------------------------------------
extern "C" void kernel_launch(void* const* d_in, const int* in_sizes, int n_in,
                              void* d_out, int out_size)
{
    const float* x    = (const float*)d_in[0];
    const float* xf   = (const float*)d_in[1];
    const float* Wq   = (const float*)d_in[2];
    const float* bq   = (const float*)d_in[3];
    const float* Wk   = (const float*)d_in[4];
    const float* bk   = (const float*)d_in[5];
    const float* Wv   = (const float*)d_in[6];
    const float* bv   = (const float*)d_in[7];
    const float* Wo   = (const float*)d_in[8];
    const float* bo   = (const float*)d_in[9];
    const float* ln_g = (const float*)d_in[10];
    const float* ln_b = (const float*)d_in[11];
    const float* W1   = (const float*)d_in[12];
    const float* b1   = (const float*)d_in[13];
    const float* W2   = (const float*)d_in[14];
    const float* b2   = (const float*)d_in[15];
    float* out = (float*)d_out;

    float *q, *k, *v, *attn, *res;
    __nv_bfloat16 *xs, *xfs, *attns, *lns, *hs, *wq, *wk, *wv, *wo, *w1, *w2;
    cudaGetSymbolAddress((void**)&q,     g_q);
    cudaGetSymbolAddress((void**)&k,     g_k);
    cudaGetSymbolAddress((void**)&v,     g_v);
    cudaGetSymbolAddress((void**)&attn,  g_attn);
    cudaGetSymbolAddress((void**)&res,   g_res);
    cudaGetSymbolAddress((void**)&xs,    g_xs);
    cudaGetSymbolAddress((void**)&xfs,   g_xfs);
    cudaGetSymbolAddress((void**)&attns, g_attns);
    cudaGetSymbolAddress((void**)&lns,   g_lns);
    cudaGetSymbolAddress((void**)&hs,    g_hs);
    cudaGetSymbolAddress((void**)&wq,    g_wq);
    cudaGetSymbolAddress((void**)&wk,    g_wk);
    cudaGetSymbolAddress((void**)&wv,    g_wv);
    cudaGetSymbolAddress((void**)&wo,    g_wo);
    cudaGetSymbolAddress((void**)&w1,    g_w1);
    cudaGetSymbolAddress((void**)&w2,    g_w2);

    const int GEMM_SMEM = NSTAGE * STAGE_BYTES;   // 96KB
    cudaFuncSetAttribute(mma_gemm<0>, cudaFuncAttributeMaxDynamicSharedMemorySize, GEMM_SMEM);
    cudaFuncSetAttribute(mma_gemm<2>, cudaFuncAttributeMaxDynamicSharedMemorySize, GEMM_SMEM);
    cudaFuncSetAttribute(mma_gemm<3>, cudaFuncAttributeMaxDynamicSharedMemorySize, GEMM_SMEM);
    const size_t attn_smem =
        (size_t)(2 * 256 * KPAD + 8 * 4 * 64 + 8 * 4 * 256) * sizeof(float);
    cudaFuncSetAttribute(attn_kernel, cudaFuncAttributeMaxDynamicSharedMemorySize,
                         (int)attn_smem);

    dim3 blk(256);
    auto cdiv = [](size_t a, size_t b) { return (unsigned)((a + b - 1) / b); };

    // weight transposition + splits
    wsplit_kernel<<<cdiv((size_t)DMODEL * DMODEL, 256), blk>>>(Wq, wq, DMODEL, DMODEL);
    wsplit_kernel<<<cdiv((size_t)DTEXT  * DMODEL, 256), blk>>>(Wk, wk, DTEXT,  DMODEL);
    wsplit_kernel<<<cdiv((size_t)DTEXT  * DMODEL, 256), blk>>>(Wv, wv, DTEXT,  DMODEL);
    wsplit_kernel<<<cdiv((size_t)DMODEL * DMODEL, 256), blk>>>(Wo, wo, DMODEL, DMODEL);
    wsplit_kernel<<<cdiv((size_t)DMODEL * DFF,    256), blk>>>(W1, w1, DMODEL, DFF);
    wsplit_kernel<<<cdiv((size_t)DFF    * DMODEL, 256), blk>>>(W2, w2, DFF,    DMODEL);
    // activation splits
    asplit_kernel<<<cdiv((size_t)MQ  * DMODEL, 256), blk>>>(x,  xs,  MQ,  DMODEL);
    asplit_kernel<<<cdiv((size_t)MKV * DTEXT,  256), blk>>>(xf, xfs, MKV, DTEXT);

    // Q = x@Wq + bq ; K/V = xf@W{k,v} + b
    mma_gemm<0><<<dim3(DMODEL / 128, MQ / 128), blk, GEMM_SMEM>>>(
        DMODEL, 3 * DMODEL, xs, wq, bq, nullptr, nullptr, q, nullptr, 0);
    mma_gemm<0><<<dim3(DMODEL / 128, MKV / 128), blk, GEMM_SMEM>>>(
        DMODEL, 3 * DTEXT, xfs, wk, bk, nullptr, nullptr, k, nullptr, 0);
    mma_gemm<0><<<dim3(DMODEL / 128, MKV / 128), blk, GEMM_SMEM>>>(
        DMODEL, 3 * DTEXT, xfs, wv, bv, nullptr, nullptr, v, nullptr, 0);

    // attention
    attn_kernel<<<BDIM * NHEADS * (TXQ / QPB), blk, attn_smem>>>(q, k, v, attn);
    asplit_kernel<<<cdiv((size_t)MQ * DMODEL, 256), blk>>>(attn, attns, MQ, DMODEL);

    // out = attn@Wo + bo (residual base)
    mma_gemm<0><<<dim3(DMODEL / 128, MQ / 128), blk, GEMM_SMEM>>>(
        DMODEL, 3 * DMODEL, attns, wo, bo, nullptr, nullptr, res, nullptr, 0);

    // LayerNorm -> split
    ln_split_kernel<<<MQ, blk>>>(res, ln_g, ln_b, lns);

    // h = GELU(ln@W1 + b1) -> split directly
    mma_gemm<2><<<dim3(DFF / 128, MQ / 128), blk, GEMM_SMEM>>>(
        DFF, 3 * DMODEL, lns, w1, b1, nullptr, nullptr, nullptr, hs, DFF);

    // final = h@W2 + b2 + res + x
    mma_gemm<3><<<dim3(DMODEL / 128, MQ / 128), blk, GEMM_SMEM>>>(
        DMODEL, 3 * DFF, hs, w2, b2, res, x, out, nullptr, 0);
}